// round 2
// baseline (speedup 1.0000x reference)
#include <cuda_runtime.h>
#include <math.h>

#define BN_    4
#define LL     2048
#define DMODEL 512
#define DI     1024
#define DI2    2048
#define DST    16
#define DTR    64
#define XD     96
#define NTOK   8192   // B * L

// ---------------- scratch (device globals: no allocation allowed) ----------------
// Live-range aliasing keeps the static footprint modest:
//   g_mo  aliases g_dt  (dt is fully consumed by the scan before mo is written)
//   g_ym  aliases g_xz[0] (xz[0] consumed by the p=0 scan's fused gating)
//   scan writes its gated output y*silu(z) IN PLACE over its u input (g_xma[p])
__device__ float g_xn  [(size_t)NTOK * DMODEL];                 // 16 MB
__device__ float g_xp  [(size_t)NTOK * DI2];                    // 64 MB
__device__ float g_xa  [(size_t)NTOK * DI];                     // 32 MB
__device__ float g_xz  [2][(size_t)NTOK * DI2];                 // 128 MB (slot 0 reused as ym)
__device__ float g_xma [2][(size_t)NTOK * DI];                  // 64 MB (reused as gated y)
__device__ float g_xdbl[2][(size_t)NTOK * XD];                  // 6 MB
__device__ float g_dt  [2][(size_t)NTOK * DI];                  // 64 MB (reused as mamba out)

__device__ __forceinline__ float siluf(float x)     { return x / (1.f + __expf(-x)); }
__device__ __forceinline__ float softplusf(float x) { return x > 20.f ? x : log1pf(__expf(x)); }

// ---------------- LayerNorm: one block per row of 512 ----------------
__global__ void ln_kernel(const float* __restrict__ x, const float* __restrict__ gg,
                          const float* __restrict__ bb, float* __restrict__ out)
{
    __shared__ float red[8];
    const int row = blockIdx.x;
    const int t   = threadIdx.x;              // 128 threads, 4 elems each
    float4 v = ((const float4*)(x + (size_t)row * DMODEL))[t];
    float s = v.x + v.y + v.z + v.w;
#pragma unroll
    for (int o = 16; o; o >>= 1) s += __shfl_xor_sync(0xffffffffu, s, o);
    if ((t & 31) == 0) red[t >> 5] = s;
    __syncthreads();
    const float mu = (red[0] + red[1] + red[2] + red[3]) * (1.f / DMODEL);
    const float dx = v.x - mu, dy = v.y - mu, dz = v.z - mu, dw = v.w - mu;
    float vs = dx*dx + dy*dy + dz*dz + dw*dw;
#pragma unroll
    for (int o = 16; o; o >>= 1) vs += __shfl_xor_sync(0xffffffffu, vs, o);
    if ((t & 31) == 0) red[4 + (t >> 5)] = vs;
    __syncthreads();
    const float var = (red[4] + red[5] + red[6] + red[7]) * (1.f / DMODEL);
    const float inv = rsqrtf(var + 1e-5f);
    const int i0 = t << 2;
    float4 o;
    o.x = dx * inv * gg[i0+0] + bb[i0+0];
    o.y = dy * inv * gg[i0+1] + bb[i0+1];
    o.z = dz * inv * gg[i0+2] + bb[i0+2];
    o.w = dw * inv * gg[i0+3] + bb[i0+3];
    ((float4*)(out + (size_t)row * DMODEL))[t] = o;
}

// ---------------- SGEMM: C[M,N] = A[M,K] @ W[N,K]^T  (both K-contiguous) ----------
// 128x128 tile, BK=16, 256 threads, 8x8 microtile. M multiple of 128, K multiple of 16.
// EPI: 0 = none, 1 = softplus(acc + bias[n]), 2 = acc + aux[m*N+n] (residual)
template<int EPI>
__global__ __launch_bounds__(256) void sgemm_nt(
    const float* __restrict__ A, int lda,
    const float* __restrict__ W,
    float* __restrict__ C,
    int N, int K,
    const float* __restrict__ aux)
{
    __shared__ float As[16][132];
    __shared__ float Bs[16][132];
    const int tid = threadIdx.x;
    const int m0 = blockIdx.y << 7;
    const int n0 = blockIdx.x << 7;
    const int ty = tid >> 4;
    const int tx = tid & 15;
    float acc[8][8];
#pragma unroll
    for (int i = 0; i < 8; i++)
#pragma unroll
        for (int j = 0; j < 8; j++) acc[i][j] = 0.f;

    for (int k0 = 0; k0 < K; k0 += 16) {
#pragma unroll
        for (int i = 0; i < 2; i++) {
            const int idx = tid + (i << 8);
            const int r  = idx >> 2;
            const int kc = (idx & 3) << 2;
            float4 va = *(const float4*)(A + (size_t)(m0 + r) * lda + (k0 + kc));
            As[kc+0][r] = va.x; As[kc+1][r] = va.y; As[kc+2][r] = va.z; As[kc+3][r] = va.w;
            float4 vb = make_float4(0.f, 0.f, 0.f, 0.f);
            if (n0 + r < N) vb = *(const float4*)(W + (size_t)(n0 + r) * K + (k0 + kc));
            Bs[kc+0][r] = vb.x; Bs[kc+1][r] = vb.y; Bs[kc+2][r] = vb.z; Bs[kc+3][r] = vb.w;
        }
        __syncthreads();
#pragma unroll
        for (int k = 0; k < 16; k++) {
            float a[8], b[8];
            *(float4*)&a[0] = *(const float4*)&As[k][(ty << 3)];
            *(float4*)&a[4] = *(const float4*)&As[k][(ty << 3) + 4];
            *(float4*)&b[0] = *(const float4*)&Bs[k][(tx << 3)];
            *(float4*)&b[4] = *(const float4*)&Bs[k][(tx << 3) + 4];
#pragma unroll
            for (int i = 0; i < 8; i++)
#pragma unroll
                for (int j = 0; j < 8; j++) acc[i][j] = fmaf(a[i], b[j], acc[i][j]);
        }
        __syncthreads();
    }
#pragma unroll
    for (int i = 0; i < 8; i++) {
        const int m = m0 + (ty << 3) + i;
#pragma unroll
        for (int j = 0; j < 8; j++) {
            const int n = n0 + (tx << 3) + j;
            if (n < N) {
                float v = acc[i][j];
                if (EPI == 1) v = softplusf(v + __ldg(&aux[n]));
                if (EPI == 2) v += __ldg(&aux[(size_t)m * N + n]);
                C[(size_t)m * N + n] = v;
            }
        }
    }
}

// ---------------- depthwise causal/anticausal conv (K=4) + SiLU -------------------
// backward path: flip(conv_causal(flip(x)))[l] == sum_j x[l+j] * w[3-j]
__global__ void conv_silu_kernel(const float* __restrict__ in, int ldin,
                                 const float* __restrict__ w, const float* __restrict__ bias,
                                 float* __restrict__ out, int backward)
{
    const int idx = blockIdx.x * 256 + threadIdx.x;     // over NTOK*DI
    const int dd  = idx & (DI - 1);
    const int tok = idx >> 10;
    const int l   = tok & (LL - 1);
    const float* base = in + (size_t)(tok - l) * ldin + dd;
    const float w0 = w[dd*4+0], w1 = w[dd*4+1], w2 = w[dd*4+2], w3 = w[dd*4+3];
    float acc = bias[dd];
    if (!backward) {
        if (l >= 3) acc += base[(size_t)(l-3)*ldin] * w0;
        if (l >= 2) acc += base[(size_t)(l-2)*ldin] * w1;
        if (l >= 1) acc += base[(size_t)(l-1)*ldin] * w2;
        acc += base[(size_t)l*ldin] * w3;
    } else {
        acc += base[(size_t)l*ldin] * w3;
        if (l+1 < LL) acc += base[(size_t)(l+1)*ldin] * w2;
        if (l+2 < LL) acc += base[(size_t)(l+2)*ldin] * w1;
        if (l+3 < LL) acc += base[(size_t)(l+3)*ldin] * w0;
    }
    out[idx] = siluf(acc);
}

// ---------------- selective scan + fused output gating ----------------
// One block = one (b, 16-d group). thread = (d_local, n). 16 lanes reduce over DSTATE.
// Chunked smem staging (64 steps). backward=1 iterates l = L-1 .. 0.
// Fused epilogue: writes  yg = (scan_y + u*D) * silu(z)  where z = xz[:, DI+d].
// NOTE: yg may alias u (in-place): each chunk stages u into smem behind a
// __syncthreads() before the store loop rewrites those addresses, and blocks own
// disjoint (b, d-group) slices. Hence no __restrict__ on u / yg.
__global__ __launch_bounds__(256) void scan_kernel(
    const float* u, const float* __restrict__ dt,
    const float* __restrict__ xdbl, const float* __restrict__ xz,
    const float* __restrict__ Alog, const float* __restrict__ Dp,
    float* yg, int backward)
{
    __shared__ float s_u[64][16], s_dt[64][16], s_B[64][16], s_C[64][16], s_y[64][16];
    const int b     = blockIdx.x >> 6;
    const int dbase = (blockIdx.x & 63) << 4;
    const int tid = threadIdx.x;
    const int dl  = tid >> 4;
    const int n   = tid & 15;
    const int d   = dbase + dl;
    const float a    = -expf(Alog[d * DST + n]);
    const float Dloc = Dp[d];
    float h = 0.f;
    const size_t brow = (size_t)b * LL;

    for (int chunk = 0; chunk < LL / 64; chunk++) {
        const int c0 = chunk << 6;
#pragma unroll
        for (int i = 0; i < 4; i++) {
            const int ii = tid + (i << 8);
            const int tt = ii >> 4, dc = ii & 15;
            const int t = c0 + tt;
            const int l = backward ? (LL - 1 - t) : t;
            const size_t roff = brow + l;
            s_u [tt][dc] = u [roff * DI + dbase + dc];
            s_dt[tt][dc] = dt[roff * DI + dbase + dc];
            s_B [tt][dc] = xdbl[roff * XD + 64 + dc];
            s_C [tt][dc] = xdbl[roff * XD + 80 + dc];
        }
        __syncthreads();
#pragma unroll 8
        for (int tt = 0; tt < 64; tt++) {
            const float dtv = s_dt[tt][dl];
            const float uv  = s_u [tt][dl];
            const float dA  = __expf(dtv * a);
            const float db  = dtv * uv * s_B[tt][n];
            h = fmaf(dA, h, db);
            float yp = h * s_C[tt][n];
            yp += __shfl_xor_sync(0xffffffffu, yp, 8);
            yp += __shfl_xor_sync(0xffffffffu, yp, 4);
            yp += __shfl_xor_sync(0xffffffffu, yp, 2);
            yp += __shfl_xor_sync(0xffffffffu, yp, 1);
            if (n == 0) s_y[tt][dl] = fmaf(uv, Dloc, yp);
        }
        __syncthreads();
#pragma unroll
        for (int i = 0; i < 4; i++) {
            const int ii = tid + (i << 8);
            const int tt = ii >> 4, dc = ii & 15;
            const int t = c0 + tt;
            const int l = backward ? (LL - 1 - t) : t;
            const size_t roff = brow + l;
            const float z = xz[roff * DI2 + DI + dbase + dc];
            yg[roff * DI + dbase + dc] = s_y[tt][dc] * siluf(z);
        }
        __syncthreads();
    }
}

// ---------------- final gate/concat ----------------
__global__ void ymix_kernel(const float* __restrict__ mo0, const float* __restrict__ mo1,
                            const float* __restrict__ xp, float* __restrict__ ym)
{
    const int idx = blockIdx.x * 256 + threadIdx.x;
    const int dd  = idx & (DI - 1);
    const int tok = idx >> 10;
    const float g = siluf(xp[(size_t)tok * DI2 + DI + dd]);
    ym[(size_t)tok * DI2 + dd]      = mo0[idx] * g;
    ym[(size_t)tok * DI2 + DI + dd] = mo1[idx] * g;
}

// ---------------- host ----------------
extern "C" void kernel_launch(void* const* d_in, const int* in_sizes, int n_in,
                              void* d_out, int out_size)
{
    const float* x      = (const float*)d_in[0];
    const float* norm_g = (const float*)d_in[1];
    const float* norm_b = (const float*)d_in[2];
    const float* in_w   = (const float*)d_in[3];
    const float* conv_w = (const float*)d_in[4];
    const float* conv_b = (const float*)d_in[5];
    const float* out_w  = (const float*)d_in[6];
    const float* P[2][9];
    for (int p = 0; p < 2; p++)
        for (int i = 0; i < 9; i++)
            P[p][i] = (const float*)d_in[7 + p * 9 + i];
    // P[p]: 0 in_w, 1 conv_w, 2 conv_b, 3 xp_w, 4 dt_w, 5 dt_b, 6 Alog, 7 D, 8 out_w

    float *xn, *xp, *xa, *xz, *xma, *xdbl, *dtb;
    cudaGetSymbolAddress((void**)&xn,   g_xn);
    cudaGetSymbolAddress((void**)&xp,   g_xp);
    cudaGetSymbolAddress((void**)&xa,   g_xa);
    cudaGetSymbolAddress((void**)&xz,   g_xz);
    cudaGetSymbolAddress((void**)&xma,  g_xma);
    cudaGetSymbolAddress((void**)&xdbl, g_xdbl);
    cudaGetSymbolAddress((void**)&dtb,  g_dt);

    float* mo = dtb;   // alias: dt fully consumed by scan before mamba-out GEMM writes
    float* ym = xz;    // alias: xz[0] fully consumed by p=0 scan's fused gating

    const int EW_GRID = NTOK * DI / 256;

    ln_kernel<<<NTOK, 128>>>(x, norm_g, norm_b, xn);

    // xp = xn @ in_w^T  (8192 x 2048, K=512)
    sgemm_nt<0><<<dim3(DI2 / 128, NTOK / 128), 256>>>(xn, DMODEL, in_w, xp, DI2, DMODEL, nullptr);

    // xa = silu(causal dwconv(xp[:, :DI]))
    conv_silu_kernel<<<EW_GRID, 256>>>(xp, DI2, conv_w, conv_b, xa, 0);

    for (int p = 0; p < 2; p++) {
        float* xzp  = xz   + (size_t)p * NTOK * DI2;
        float* xmap = xma  + (size_t)p * NTOK * DI;
        float* xdp  = xdbl + (size_t)p * NTOK * XD;
        float* dtp  = dtb  + (size_t)p * NTOK * DI;
        float* mop  = mo   + (size_t)p * NTOK * DI;   // same memory as dtp

        // xz = xa @ p_in_w^T  (8192 x 2048, K=1024) — flips are pointwise in L, elided
        sgemm_nt<0><<<dim3(DI2 / 128, NTOK / 128), 256>>>(xa, DI, P[p][0], xzp, DI2, DI, nullptr);
        // xm = silu(dwconv(xz[:, :DI]))  causal (p=0) / anticausal-reversed (p=1)
        conv_silu_kernel<<<EW_GRID, 256>>>(xzp, DI2, P[p][1], P[p][2], xmap, p);
        // xdbl = xm @ xp_w^T  (8192 x 96, K=1024)
        sgemm_nt<0><<<dim3(1, NTOK / 128), 256>>>(xmap, DI, P[p][3], xdp, XD, DI, nullptr);
        // dt = softplus(xdbl[:, :64] @ dt_w^T + dt_b)  (8192 x 1024, K=64, lda=96)
        sgemm_nt<1><<<dim3(DI / 128, NTOK / 128), 256>>>(xdp, XD, P[p][4], dtp, DI, DTR, P[p][5]);
        // selective scan + fused  y*silu(z)  gating, written in place over xmap
        scan_kernel<<<BN_ * (DI / 16), 256>>>(xmap, dtp, xdp, xzp, P[p][6], P[p][7], xmap, p);
        // mamba out = yg @ out_w^T (8192 x 1024, K=1024); mop aliases dtp (dt dead here)
        sgemm_nt<0><<<dim3(DI / 128, NTOK / 128), 256>>>(xmap, DI, P[p][8], mop, DI, DI, nullptr);
    }

    // ym = [yf*g, yb*g],  g = silu(xp[:, DI:]); ym aliases xz[0] (dead)
    ymix_kernel<<<EW_GRID, 256>>>(mo, mo + (size_t)NTOK * DI, xp, ym);

    // out = ym @ out_w^T + x  (8192 x 512, K=2048)
    sgemm_nt<2><<<dim3(DMODEL / 128, NTOK / 128), 256>>>(ym, DI2, out_w, (float*)d_out, DMODEL, DI2, x);
}

// round 3
// speedup vs baseline: 1.2914x; 1.2914x over previous
#include <cuda_runtime.h>
#include <math.h>
#include <stdint.h>

#define BN_    4
#define LL     2048
#define DMODEL 512
#define DI     1024
#define DI2    2048
#define DST    16
#define DTR    64
#define XD     96
#define NTOK   8192   // B * L

// ---------------- scratch (device globals: no allocation allowed) ----------------
// Live-range aliasing:
//   mamba-out aliases g_dt (dt fully consumed by the scan first)
//   ym aliases g_xz[0] (consumed by p=0 scan's fused gating)
//   scan writes gated output in place over its u input (g_xma[p])
__device__ float g_xn  [(size_t)NTOK * DMODEL];
__device__ float g_xp  [(size_t)NTOK * DI2];
__device__ float g_xa  [(size_t)NTOK * DI];
__device__ float g_xz  [2][(size_t)NTOK * DI2];
__device__ float g_xma [2][(size_t)NTOK * DI];
__device__ float g_xdbl[2][(size_t)NTOK * XD];
__device__ float g_dt  [2][(size_t)NTOK * DI];

__device__ __forceinline__ float siluf(float x)     { return x / (1.f + __expf(-x)); }
__device__ __forceinline__ float softplusf(float x) { return x > 20.f ? x : log1pf(__expf(x)); }

// ---------------- LayerNorm ----------------
__global__ void ln_kernel(const float* __restrict__ x, const float* __restrict__ gg,
                          const float* __restrict__ bb, float* __restrict__ out)
{
    __shared__ float red[8];
    const int row = blockIdx.x;
    const int t   = threadIdx.x;
    float4 v = ((const float4*)(x + (size_t)row * DMODEL))[t];
    float s = v.x + v.y + v.z + v.w;
#pragma unroll
    for (int o = 16; o; o >>= 1) s += __shfl_xor_sync(0xffffffffu, s, o);
    if ((t & 31) == 0) red[t >> 5] = s;
    __syncthreads();
    const float mu = (red[0] + red[1] + red[2] + red[3]) * (1.f / DMODEL);
    const float dx = v.x - mu, dy = v.y - mu, dz = v.z - mu, dw = v.w - mu;
    float vs = dx*dx + dy*dy + dz*dz + dw*dw;
#pragma unroll
    for (int o = 16; o; o >>= 1) vs += __shfl_xor_sync(0xffffffffu, vs, o);
    if ((t & 31) == 0) red[4 + (t >> 5)] = vs;
    __syncthreads();
    const float var = (red[4] + red[5] + red[6] + red[7]) * (1.f / DMODEL);
    const float inv = rsqrtf(var + 1e-5f);
    const int i0 = t << 2;
    float4 o;
    o.x = dx * inv * gg[i0+0] + bb[i0+0];
    o.y = dy * inv * gg[i0+1] + bb[i0+1];
    o.z = dz * inv * gg[i0+2] + bb[i0+2];
    o.w = dw * inv * gg[i0+3] + bb[i0+3];
    ((float4*)(out + (size_t)row * DMODEL))[t] = o;
}

// ---------------- bf16x2 helpers ----------------
__device__ __forceinline__ uint32_t pack_bf16x2(float x, float y) {
    uint32_t r;
    asm("cvt.rn.bf16x2.f32 %0, %1, %2;" : "=r"(r) : "f"(y), "f"(x));  // {lo=x, hi=y}
    return r;
}

__device__ __forceinline__ void mma_bf16(float* c, const uint32_t* a, const uint32_t* b) {
    asm volatile("mma.sync.aligned.m16n8k16.row.col.f32.bf16.bf16.f32 "
        "{%0,%1,%2,%3}, {%4,%5,%6,%7}, {%8,%9}, {%0,%1,%2,%3};"
        : "+f"(c[0]), "+f"(c[1]), "+f"(c[2]), "+f"(c[3])
        : "r"(a[0]), "r"(a[1]), "r"(a[2]), "r"(a[3]), "r"(b[0]), "r"(b[1]));
}

// ---------------- tensor-core GEMM (split-bf16, ~fp32-precision) ----------------
// C[M,N] = A[M,K] @ W[N,K]^T.  M mult of 128, K mult of 16, N arbitrary (zero-pad).
// Block 128x128, BK=16, 128 threads = 4 warps of 64x64 (2x2).
// EPI: 0 none, 1 softplus(acc + bias[n]), 2 acc + aux[m*N+n]
template<int EPI>
__global__ __launch_bounds__(128, 2) void gemm_tc(
    const float* __restrict__ A, int lda,
    const float* __restrict__ W,
    float* __restrict__ C, int N, int K,
    const float* __restrict__ aux)
{
    __shared__ uint32_t sAh[8][136], sAl[8][136], sBh[8][136], sBl[8][136];
    const int tid  = threadIdx.x;
    const int m0   = blockIdx.y << 7;
    const int n0   = blockIdx.x << 7;
    const int lane = tid & 31, warp = tid >> 5;
    const int wm = (warp >> 1) << 6, wn = (warp & 1) << 6;
    const int g  = lane >> 2,  t  = lane & 3;

    float acc[4][8][4];
#pragma unroll
    for (int i = 0; i < 4; i++)
#pragma unroll
        for (int j = 0; j < 8; j++)
#pragma unroll
            for (int q = 0; q < 4; q++) acc[i][j][q] = 0.f;

#pragma unroll 1
    for (int k0 = 0; k0 < K; k0 += 16) {
#pragma unroll
        for (int it = 0; it < 4; it++) {
            const int idx = tid + (it << 7);          // 0..511
            const int r   = idx >> 2;                  // row 0..127
            const int kc  = (idx & 3) << 2;            // 0,4,8,12
            const int k2  = kc >> 1;
            // A
            float4 v = *(const float4*)(A + (size_t)(m0 + r) * lda + k0 + kc);
            uint32_t h0 = pack_bf16x2(v.x, v.y);
            uint32_t h1 = pack_bf16x2(v.z, v.w);
            float rx = __uint_as_float(h0 << 16);
            float ry = __uint_as_float(h0 & 0xffff0000u);
            float rz = __uint_as_float(h1 << 16);
            float rw = __uint_as_float(h1 & 0xffff0000u);
            sAh[k2][r]   = h0; sAh[k2+1][r] = h1;
            sAl[k2][r]   = pack_bf16x2(v.x - rx, v.y - ry);
            sAl[k2+1][r] = pack_bf16x2(v.z - rz, v.w - rw);
            // B (zero-pad rows beyond N)
            float4 w4 = make_float4(0.f, 0.f, 0.f, 0.f);
            if (n0 + r < N) w4 = *(const float4*)(W + (size_t)(n0 + r) * K + k0 + kc);
            uint32_t g0 = pack_bf16x2(w4.x, w4.y);
            uint32_t g1 = pack_bf16x2(w4.z, w4.w);
            float sx = __uint_as_float(g0 << 16);
            float sy = __uint_as_float(g0 & 0xffff0000u);
            float sz = __uint_as_float(g1 << 16);
            float sw = __uint_as_float(g1 & 0xffff0000u);
            sBh[k2][r]   = g0; sBh[k2+1][r] = g1;
            sBl[k2][r]   = pack_bf16x2(w4.x - sx, w4.y - sy);
            sBl[k2+1][r] = pack_bf16x2(w4.z - sz, w4.w - sw);
        }
        __syncthreads();

        uint32_t bh[8][2], bl[8][2];
#pragma unroll
        for (int nt = 0; nt < 8; nt++) {
            const int nb = wn + (nt << 3) + g;
            bh[nt][0] = sBh[t][nb];     bh[nt][1] = sBh[t+4][nb];
            bl[nt][0] = sBl[t][nb];     bl[nt][1] = sBl[t+4][nb];
        }
#pragma unroll
        for (int mt = 0; mt < 4; mt++) {
            const int mb = wm + (mt << 4) + g;
            uint32_t ah[4] = { sAh[t][mb], sAh[t][mb+8], sAh[t+4][mb], sAh[t+4][mb+8] };
            uint32_t al[4] = { sAl[t][mb], sAl[t][mb+8], sAl[t+4][mb], sAl[t+4][mb+8] };
#pragma unroll
            for (int nt = 0; nt < 8; nt++) {
                mma_bf16(acc[mt][nt], ah, bh[nt]);   // hi*hi
                mma_bf16(acc[mt][nt], ah, bl[nt]);   // hi*lo
                mma_bf16(acc[mt][nt], al, bh[nt]);   // lo*hi
            }
        }
        __syncthreads();
    }

    // epilogue: c0,c1 at (row, col..col+1), c2,c3 at (row+8, ...)
#pragma unroll
    for (int mt = 0; mt < 4; mt++) {
        const int r0 = m0 + wm + (mt << 4) + g;
#pragma unroll
        for (int nt = 0; nt < 8; nt++) {
            const int col = n0 + wn + (nt << 3) + (t << 1);
            if (col < N) {
                float v0 = acc[mt][nt][0], v1 = acc[mt][nt][1];
                float v2 = acc[mt][nt][2], v3 = acc[mt][nt][3];
                if (EPI == 1) {
                    const float b0 = __ldg(&aux[col]), b1 = __ldg(&aux[col+1]);
                    v0 = softplusf(v0 + b0); v1 = softplusf(v1 + b1);
                    v2 = softplusf(v2 + b0); v3 = softplusf(v3 + b1);
                }
                if (EPI == 2) {
                    const float2 a0 = *(const float2*)(aux + (size_t)r0 * N + col);
                    const float2 a1 = *(const float2*)(aux + (size_t)(r0+8) * N + col);
                    v0 += a0.x; v1 += a0.y; v2 += a1.x; v3 += a1.y;
                }
                *(float2*)(C + (size_t)r0     * N + col) = make_float2(v0, v1);
                *(float2*)(C + (size_t)(r0+8) * N + col) = make_float2(v2, v3);
            }
        }
    }
}

// ---------------- fp32 SIMT SGEMM (kept for the dt GEMM: exp-amplified path) -----
template<int EPI>
__global__ __launch_bounds__(256) void sgemm_nt(
    const float* __restrict__ A, int lda,
    const float* __restrict__ W,
    float* __restrict__ C,
    int N, int K,
    const float* __restrict__ aux)
{
    __shared__ float As[16][132];
    __shared__ float Bs[16][132];
    const int tid = threadIdx.x;
    const int m0 = blockIdx.y << 7;
    const int n0 = blockIdx.x << 7;
    const int ty = tid >> 4;
    const int tx = tid & 15;
    float acc[8][8];
#pragma unroll
    for (int i = 0; i < 8; i++)
#pragma unroll
        for (int j = 0; j < 8; j++) acc[i][j] = 0.f;

    for (int k0 = 0; k0 < K; k0 += 16) {
#pragma unroll
        for (int i = 0; i < 2; i++) {
            const int idx = tid + (i << 8);
            const int r  = idx >> 2;
            const int kc = (idx & 3) << 2;
            float4 va = *(const float4*)(A + (size_t)(m0 + r) * lda + (k0 + kc));
            As[kc+0][r] = va.x; As[kc+1][r] = va.y; As[kc+2][r] = va.z; As[kc+3][r] = va.w;
            float4 vb = make_float4(0.f, 0.f, 0.f, 0.f);
            if (n0 + r < N) vb = *(const float4*)(W + (size_t)(n0 + r) * K + (k0 + kc));
            Bs[kc+0][r] = vb.x; Bs[kc+1][r] = vb.y; Bs[kc+2][r] = vb.z; Bs[kc+3][r] = vb.w;
        }
        __syncthreads();
#pragma unroll
        for (int k = 0; k < 16; k++) {
            float a[8], b[8];
            *(float4*)&a[0] = *(const float4*)&As[k][(ty << 3)];
            *(float4*)&a[4] = *(const float4*)&As[k][(ty << 3) + 4];
            *(float4*)&b[0] = *(const float4*)&Bs[k][(tx << 3)];
            *(float4*)&b[4] = *(const float4*)&Bs[k][(tx << 3) + 4];
#pragma unroll
            for (int i = 0; i < 8; i++)
#pragma unroll
                for (int j = 0; j < 8; j++) acc[i][j] = fmaf(a[i], b[j], acc[i][j]);
        }
        __syncthreads();
    }
#pragma unroll
    for (int i = 0; i < 8; i++) {
        const int m = m0 + (ty << 3) + i;
#pragma unroll
        for (int j = 0; j < 8; j++) {
            const int n = n0 + (tx << 3) + j;
            if (n < N) {
                float v = acc[i][j];
                if (EPI == 1) v = softplusf(v + __ldg(&aux[n]));
                C[(size_t)m * N + n] = v;
            }
        }
    }
}

// ---------------- depthwise causal/anticausal conv (K=4) + SiLU -------------------
__global__ void conv_silu_kernel(const float* __restrict__ in, int ldin,
                                 const float* __restrict__ w, const float* __restrict__ bias,
                                 float* __restrict__ out, int backward)
{
    const int idx = blockIdx.x * 256 + threadIdx.x;
    const int dd  = idx & (DI - 1);
    const int tok = idx >> 10;
    const int l   = tok & (LL - 1);
    const float* base = in + (size_t)(tok - l) * ldin + dd;
    const float w0 = w[dd*4+0], w1 = w[dd*4+1], w2 = w[dd*4+2], w3 = w[dd*4+3];
    float acc = bias[dd];
    if (!backward) {
        if (l >= 3) acc += base[(size_t)(l-3)*ldin] * w0;
        if (l >= 2) acc += base[(size_t)(l-2)*ldin] * w1;
        if (l >= 1) acc += base[(size_t)(l-1)*ldin] * w2;
        acc += base[(size_t)l*ldin] * w3;
    } else {
        acc += base[(size_t)l*ldin] * w3;
        if (l+1 < LL) acc += base[(size_t)(l+1)*ldin] * w2;
        if (l+2 < LL) acc += base[(size_t)(l+2)*ldin] * w1;
        if (l+3 < LL) acc += base[(size_t)(l+3)*ldin] * w0;
    }
    out[idx] = siluf(acc);
}

// ---------------- selective scan + fused output gating ----------------
__global__ __launch_bounds__(256) void scan_kernel(
    const float* u, const float* __restrict__ dt,
    const float* __restrict__ xdbl, const float* __restrict__ xz,
    const float* __restrict__ Alog, const float* __restrict__ Dp,
    float* yg, int backward)
{
    __shared__ float s_u[64][16], s_dt[64][16], s_B[64][16], s_C[64][16], s_y[64][16];
    const int b     = blockIdx.x >> 6;
    const int dbase = (blockIdx.x & 63) << 4;
    const int tid = threadIdx.x;
    const int dl  = tid >> 4;
    const int n   = tid & 15;
    const int d   = dbase + dl;
    const float a    = -expf(Alog[d * DST + n]);
    const float Dloc = Dp[d];
    float h = 0.f;
    const size_t brow = (size_t)b * LL;

    for (int chunk = 0; chunk < LL / 64; chunk++) {
        const int c0 = chunk << 6;
#pragma unroll
        for (int i = 0; i < 4; i++) {
            const int ii = tid + (i << 8);
            const int tt = ii >> 4, dc = ii & 15;
            const int t = c0 + tt;
            const int l = backward ? (LL - 1 - t) : t;
            const size_t roff = brow + l;
            s_u [tt][dc] = u [roff * DI + dbase + dc];
            s_dt[tt][dc] = dt[roff * DI + dbase + dc];
            s_B [tt][dc] = xdbl[roff * XD + 64 + dc];
            s_C [tt][dc] = xdbl[roff * XD + 80 + dc];
        }
        __syncthreads();
#pragma unroll 8
        for (int tt = 0; tt < 64; tt++) {
            const float dtv = s_dt[tt][dl];
            const float uv  = s_u [tt][dl];
            const float dA  = __expf(dtv * a);
            const float db  = dtv * uv * s_B[tt][n];
            h = fmaf(dA, h, db);
            float yp = h * s_C[tt][n];
            yp += __shfl_xor_sync(0xffffffffu, yp, 8);
            yp += __shfl_xor_sync(0xffffffffu, yp, 4);
            yp += __shfl_xor_sync(0xffffffffu, yp, 2);
            yp += __shfl_xor_sync(0xffffffffu, yp, 1);
            if (n == 0) s_y[tt][dl] = fmaf(uv, Dloc, yp);
        }
        __syncthreads();
#pragma unroll
        for (int i = 0; i < 4; i++) {
            const int ii = tid + (i << 8);
            const int tt = ii >> 4, dc = ii & 15;
            const int t = c0 + tt;
            const int l = backward ? (LL - 1 - t) : t;
            const size_t roff = brow + l;
            const float z = xz[roff * DI2 + DI + dbase + dc];
            yg[roff * DI + dbase + dc] = s_y[tt][dc] * siluf(z);
        }
        __syncthreads();
    }
}

// ---------------- final gate/concat ----------------
__global__ void ymix_kernel(const float* __restrict__ mo0, const float* __restrict__ mo1,
                            const float* __restrict__ xp, float* __restrict__ ym)
{
    const int idx = blockIdx.x * 256 + threadIdx.x;
    const int dd  = idx & (DI - 1);
    const int tok = idx >> 10;
    const float g = siluf(xp[(size_t)tok * DI2 + DI + dd]);
    ym[(size_t)tok * DI2 + dd]      = mo0[idx] * g;
    ym[(size_t)tok * DI2 + DI + dd] = mo1[idx] * g;
}

// ---------------- host ----------------
extern "C" void kernel_launch(void* const* d_in, const int* in_sizes, int n_in,
                              void* d_out, int out_size)
{
    const float* x      = (const float*)d_in[0];
    const float* norm_g = (const float*)d_in[1];
    const float* norm_b = (const float*)d_in[2];
    const float* in_w   = (const float*)d_in[3];
    const float* conv_w = (const float*)d_in[4];
    const float* conv_b = (const float*)d_in[5];
    const float* out_w  = (const float*)d_in[6];
    const float* P[2][9];
    for (int p = 0; p < 2; p++)
        for (int i = 0; i < 9; i++)
            P[p][i] = (const float*)d_in[7 + p * 9 + i];
    // P[p]: 0 in_w, 1 conv_w, 2 conv_b, 3 xp_w, 4 dt_w, 5 dt_b, 6 Alog, 7 D, 8 out_w

    float *xn, *xp, *xa, *xz, *xma, *xdbl, *dtb;
    cudaGetSymbolAddress((void**)&xn,   g_xn);
    cudaGetSymbolAddress((void**)&xp,   g_xp);
    cudaGetSymbolAddress((void**)&xa,   g_xa);
    cudaGetSymbolAddress((void**)&xz,   g_xz);
    cudaGetSymbolAddress((void**)&xma,  g_xma);
    cudaGetSymbolAddress((void**)&xdbl, g_xdbl);
    cudaGetSymbolAddress((void**)&dtb,  g_dt);

    float* mo = dtb;   // alias: dt fully consumed by scan before mamba-out GEMM writes
    float* ym = xz;    // alias: xz[0] fully consumed by p=0 scan's fused gating

    const int EW_GRID = NTOK * DI / 256;
    const int MB = NTOK / 128;   // 64 M-blocks

    ln_kernel<<<NTOK, 128>>>(x, norm_g, norm_b, xn);

    // xp = xn @ in_w^T  (8192 x 2048, K=512)
    gemm_tc<0><<<dim3(DI2 / 128, MB), 128>>>(xn, DMODEL, in_w, xp, DI2, DMODEL, nullptr);

    // xa = silu(causal dwconv(xp[:, :DI]))
    conv_silu_kernel<<<EW_GRID, 256>>>(xp, DI2, conv_w, conv_b, xa, 0);

    for (int p = 0; p < 2; p++) {
        float* xzp  = xz   + (size_t)p * NTOK * DI2;
        float* xmap = xma  + (size_t)p * NTOK * DI;
        float* xdp  = xdbl + (size_t)p * NTOK * XD;
        float* dtp  = dtb  + (size_t)p * NTOK * DI;
        float* mop  = mo   + (size_t)p * NTOK * DI;   // same memory as dtp

        // xz = xa @ p_in_w^T  (8192 x 2048, K=1024) — flips pointwise in L, elided
        gemm_tc<0><<<dim3(DI2 / 128, MB), 128>>>(xa, DI, P[p][0], xzp, DI2, DI, nullptr);
        // xm = silu(dwconv(xz[:, :DI]))  causal (p=0) / anticausal-reversed (p=1)
        conv_silu_kernel<<<EW_GRID, 256>>>(xzp, DI2, P[p][1], P[p][2], xmap, p);
        // xdbl = xm @ xp_w^T  (8192 x 96, K=1024)
        gemm_tc<0><<<dim3(1, MB), 128>>>(xmap, DI, P[p][3], xdp, XD, DI, nullptr);
        // dt = softplus(xdbl[:, :64] @ dt_w^T + dt_b) — fp32 SIMT (exp-amplified path)
        sgemm_nt<1><<<dim3(DI / 128, MB), 256>>>(xdp, XD, P[p][4], dtp, DI, DTR, P[p][5]);
        // selective scan + fused  y*silu(z)  gating, in place over xmap
        scan_kernel<<<BN_ * (DI / 16), 256>>>(xmap, dtp, xdp, xzp, P[p][6], P[p][7], xmap, p);
        // mamba out = yg @ out_w^T (8192 x 1024, K=1024); mop aliases dtp (dt dead)
        gemm_tc<0><<<dim3(DI / 128, MB), 128>>>(xmap, DI, P[p][8], mop, DI, DI, nullptr);
    }

    // ym = [yf*g, yb*g],  g = silu(xp[:, DI:]); ym aliases xz[0] (dead)
    ymix_kernel<<<EW_GRID, 256>>>(mo, mo + (size_t)NTOK * DI, xp, ym);

    // out = ym @ out_w^T + x  (8192 x 512, K=2048)
    gemm_tc<2><<<dim3(DMODEL / 128, MB), 128>>>(ym, DI2, out_w, (float*)d_out, DMODEL, DI2, x);
}

// round 5
// speedup vs baseline: 2.1389x; 1.6563x over previous
#include <cuda_runtime.h>
#include <math.h>
#include <stdint.h>

#define BN_    4
#define LL     2048
#define DMODEL 512
#define DI     1024
#define DI2    2048
#define DST    16
#define DTR    64
#define XD     96
#define NTOK   8192   // B * L

// tcgen05 only exists on the arch-specific target (sm_103a / sm_100a).
#if defined(__CUDA_ARCH_FEAT_SM103_ALL) || defined(__CUDA_ARCH_FEAT_SM100_ALL)
#define HAS_TC5 1
#endif

// ---------------- scratch (device globals: no allocation allowed) ----------------
__device__ float g_xn  [(size_t)NTOK * DMODEL];
__device__ float g_xp  [(size_t)NTOK * DI2];
__device__ float g_xa  [(size_t)NTOK * DI];
__device__ float g_xz  [2][(size_t)NTOK * DI2];
__device__ float g_xma [2][(size_t)NTOK * DI];
__device__ float g_xdbl[2][(size_t)NTOK * XD];
__device__ float g_dt  [2][(size_t)NTOK * DI];

__device__ __forceinline__ float siluf(float x)     { return x / (1.f + __expf(-x)); }
__device__ __forceinline__ float softplusf(float x) { return x > 20.f ? x : log1pf(__expf(x)); }

// ---------------- LayerNorm ----------------
__global__ void ln_kernel(const float* __restrict__ x, const float* __restrict__ gg,
                          const float* __restrict__ bb, float* __restrict__ out)
{
    __shared__ float red[8];
    const int row = blockIdx.x;
    const int t   = threadIdx.x;
    float4 v = ((const float4*)(x + (size_t)row * DMODEL))[t];
    float s = v.x + v.y + v.z + v.w;
#pragma unroll
    for (int o = 16; o; o >>= 1) s += __shfl_xor_sync(0xffffffffu, s, o);
    if ((t & 31) == 0) red[t >> 5] = s;
    __syncthreads();
    const float mu = (red[0] + red[1] + red[2] + red[3]) * (1.f / DMODEL);
    const float dx = v.x - mu, dy = v.y - mu, dz = v.z - mu, dw = v.w - mu;
    float vs = dx*dx + dy*dy + dz*dz + dw*dw;
#pragma unroll
    for (int o = 16; o; o >>= 1) vs += __shfl_xor_sync(0xffffffffu, vs, o);
    if ((t & 31) == 0) red[4 + (t >> 5)] = vs;
    __syncthreads();
    const float var = (red[4] + red[5] + red[6] + red[7]) * (1.f / DMODEL);
    const float inv = rsqrtf(var + 1e-5f);
    const int i0 = t << 2;
    float4 o;
    o.x = dx * inv * gg[i0+0] + bb[i0+0];
    o.y = dy * inv * gg[i0+1] + bb[i0+1];
    o.z = dz * inv * gg[i0+2] + bb[i0+2];
    o.w = dw * inv * gg[i0+3] + bb[i0+3];
    ((float4*)(out + (size_t)row * DMODEL))[t] = o;
}

// ---------------- shared helpers ----------------
__device__ __forceinline__ uint32_t pack_bf16x2(float x, float y) {
    uint32_t r;
    asm("cvt.rn.bf16x2.f32 %0, %1, %2;" : "=r"(r) : "f"(y), "f"(x));  // {lo=x, hi=y}
    return r;
}

#ifdef HAS_TC5
// ---------------- tcgen05 helpers ----------------
__device__ __forceinline__ uint32_t smem_u32(const void* p) {
    uint32_t a;
    asm("{ .reg .u64 t; cvta.to.shared.u64 t, %1; cvt.u32.u64 %0, t; }" : "=r"(a) : "l"(p));
    return a;
}
__device__ __forceinline__ uint32_t elect1() {
    uint32_t p;
    asm volatile("{\n\t.reg .pred p;\n\telect.sync _|p, 0xFFFFFFFF;\n\tselp.b32 %0, 1, 0, p;\n\t}"
                 : "=r"(p));
    return p;
}
__device__ __forceinline__ uint32_t swz(uint32_t off) { return off ^ ((off >> 3) & 0x70); }

// SW128 K-major smem descriptor (Blackwell): layout=2, version=1, SBO=64, LBO=1
static __device__ __forceinline__ uint64_t mkdesc(uint32_t addr) {
    const uint64_t base = (2ull << 61) | (1ull << 46) | (64ull << 32) | (1ull << 16);
    return base | ((addr >> 4) & 0x3FFFu);
}

__device__ __forceinline__ void mma_f16_ss(uint32_t d, uint64_t a, uint64_t b,
                                           uint32_t idesc, uint32_t en) {
    asm volatile(
        "{\n\t.reg .pred p;\n\tsetp.ne.u32 p, %4, 0;\n\t"
        "tcgen05.mma.cta_group::1.kind::f16 [%0], %1, %2, %3, {%5,%5,%5,%5}, p;\n\t}"
        :: "r"(d), "l"(a), "l"(b), "r"(idesc), "r"(en), "r"(0u) : "memory");
}

__device__ __forceinline__ void mbar_wait(uint32_t mbar, uint32_t parity) {
    asm volatile(
        "{\n\t.reg .pred P;\n\t"
        "W_%=:\n\t"
        "mbarrier.try_wait.parity.acquire.cta.shared::cta.b64 P, [%0], %1, 0x989680;\n\t"
        "@P bra.uni D_%=;\n\t"
        "bra.uni W_%=;\n\t"
        "D_%=:\n\t}"
        :: "r"(mbar), "r"(parity) : "memory");
}

#define TC_LD32(r, addr) \
    asm volatile( \
        "tcgen05.ld.sync.aligned.32x32b.x32.b32 " \
        "{%0, %1, %2, %3, %4, %5, %6, %7, " \
        " %8, %9, %10, %11, %12, %13, %14, %15, " \
        " %16, %17, %18, %19, %20, %21, %22, %23, " \
        " %24, %25, %26, %27, %28, %29, %30, %31}, [%32];" \
        : "=r"((r)[0]),  "=r"((r)[1]),  "=r"((r)[2]),  "=r"((r)[3]), \
          "=r"((r)[4]),  "=r"((r)[5]),  "=r"((r)[6]),  "=r"((r)[7]), \
          "=r"((r)[8]),  "=r"((r)[9]),  "=r"((r)[10]), "=r"((r)[11]), \
          "=r"((r)[12]), "=r"((r)[13]), "=r"((r)[14]), "=r"((r)[15]), \
          "=r"((r)[16]), "=r"((r)[17]), "=r"((r)[18]), "=r"((r)[19]), \
          "=r"((r)[20]), "=r"((r)[21]), "=r"((r)[22]), "=r"((r)[23]), \
          "=r"((r)[24]), "=r"((r)[25]), "=r"((r)[26]), "=r"((r)[27]), \
          "=r"((r)[28]), "=r"((r)[29]), "=r"((r)[30]), "=r"((r)[31]) \
        : "r"(addr))
#else
// ---------------- mma.sync helper (fallback HMMA path, proven in R3) ----------------
__device__ __forceinline__ void mma_bf16(float* c, const uint32_t* a, const uint32_t* b) {
    asm volatile("mma.sync.aligned.m16n8k16.row.col.f32.bf16.bf16.f32 "
        "{%0,%1,%2,%3}, {%4,%5,%6,%7}, {%8,%9}, {%0,%1,%2,%3};"
        : "+f"(c[0]), "+f"(c[1]), "+f"(c[2]), "+f"(c[3])
        : "r"(a[0]), "r"(a[1]), "r"(a[2]), "r"(a[3]), "r"(b[0]), "r"(b[1]));
}
#endif

// ---------------- GEMM: C[M,N] = A[M,K] @ W[N,K]^T, split-bf16 3-pass ----------------
// M mult of 128, K mult of 64, N mult of 4 (tile zero-padded to 128).
// EPI: 0 none, 1 softplus(acc+bias[n]), 2 acc+aux[m*N+n].
#define SM_AH 1024
#define SM_AL 17408
#define SM_BH 33792
#define SM_BL 50176
#define SM_TOT 66560

template<int EPI>
__global__ void __launch_bounds__(128)
gemm5(const float* __restrict__ A, int lda, const float* __restrict__ W,
      float* __restrict__ C, int N, int K, const float* __restrict__ aux)
{
#ifdef HAS_TC5
    // ================= tcgen05 path (sm_103a SASS) =================
    extern __shared__ __align__(1024) char sm[];
    const uint32_t sb = smem_u32(sm);
    const int tid = threadIdx.x, warp = tid >> 5, lane = tid & 31;
    const int m0 = blockIdx.y << 7, n0 = blockIdx.x << 7;

    if (warp == 0) {
        asm volatile("tcgen05.alloc.cta_group::1.sync.aligned.shared::cta.b32 [%0], %1;"
                     :: "r"(sb), "r"(128u) : "memory");
        asm volatile("tcgen05.relinquish_alloc_permit.cta_group::1.sync.aligned;");
    }
    if (tid == 0)
        asm volatile("mbarrier.init.shared.b64 [%0], %1;" :: "r"(sb + 8), "r"(1u) : "memory");
    __syncthreads();
    uint32_t tmem;
    asm volatile("ld.shared.b32 %0, [%1];" : "=r"(tmem) : "r"(sb));

    const uint32_t idesc = 0x8200490u;   // M=128, N=128, bf16 x bf16 -> f32
    uint32_t phase = 0;

    for (int k0 = 0; k0 < K; k0 += 64) {
#pragma unroll
        for (int i = 0; i < 16; i++) {
            const int ii = tid + (i << 7);
            const int r  = ii >> 4;          // tile row 0..127
            const int c4 = ii & 15;          // float4 index (64 floats/row)
            const uint32_t sw = swz((uint32_t)(r * 128 + c4 * 8));
            float4 v = *(const float4*)(A + (size_t)(m0 + r) * lda + k0 + (c4 << 2));
            uint32_t h0 = pack_bf16x2(v.x, v.y);
            uint32_t h1 = pack_bf16x2(v.z, v.w);
            float rx = __uint_as_float(h0 << 16), ry = __uint_as_float(h0 & 0xffff0000u);
            float rz = __uint_as_float(h1 << 16), rw = __uint_as_float(h1 & 0xffff0000u);
            *(uint2*)(sm + SM_AH + sw) = make_uint2(h0, h1);
            *(uint2*)(sm + SM_AL + sw) =
                make_uint2(pack_bf16x2(v.x - rx, v.y - ry), pack_bf16x2(v.z - rz, v.w - rw));
            float4 w4 = make_float4(0.f, 0.f, 0.f, 0.f);
            if (n0 + r < N) w4 = *(const float4*)(W + (size_t)(n0 + r) * K + k0 + (c4 << 2));
            uint32_t g0 = pack_bf16x2(w4.x, w4.y);
            uint32_t g1 = pack_bf16x2(w4.z, w4.w);
            float sx = __uint_as_float(g0 << 16), sy = __uint_as_float(g0 & 0xffff0000u);
            float sz = __uint_as_float(g1 << 16), sw2 = __uint_as_float(g1 & 0xffff0000u);
            *(uint2*)(sm + SM_BH + sw) = make_uint2(g0, g1);
            *(uint2*)(sm + SM_BL + sw) =
                make_uint2(pack_bf16x2(w4.x - sx, w4.y - sy), pack_bf16x2(w4.z - sz, w4.w - sw2));
        }
        asm volatile("fence.proxy.async.shared::cta;" ::: "memory");
        __syncthreads();

        if (warp == 0 && elect1()) {
            const uint64_t ah = mkdesc(sb + SM_AH), al = mkdesc(sb + SM_AL);
            const uint64_t bh = mkdesc(sb + SM_BH), bl = mkdesc(sb + SM_BL);
#pragma unroll
            for (int kc = 0; kc < 4; kc++) {
                mma_f16_ss(tmem, ah + kc * 2, bh + kc * 2, idesc, (k0 | kc) != 0);
                mma_f16_ss(tmem, ah + kc * 2, bl + kc * 2, idesc, 1u);
                mma_f16_ss(tmem, al + kc * 2, bh + kc * 2, idesc, 1u);
            }
            asm volatile(
                "tcgen05.commit.cta_group::1.mbarrier::arrive::one.shared::cluster.b64 [%0];"
                :: "r"(sb + 8) : "memory");
        }
        mbar_wait(sb + 8, phase);
        phase ^= 1;
    }

    asm volatile("tcgen05.fence::after_thread_sync;" ::: "memory");

    const int m = m0 + warp * 32 + lane;
#pragma unroll
    for (int base = 0; base < 128; base += 32) {
        uint32_t r[32];
        TC_LD32(r, tmem + base);
        asm volatile("tcgen05.wait::ld.sync.aligned;" ::: "memory");
#pragma unroll
        for (int j = 0; j < 32; j += 4) {
            const int col = n0 + base + j;
            if (col < N) {
                float4 v = make_float4(__uint_as_float(r[j]),   __uint_as_float(r[j+1]),
                                       __uint_as_float(r[j+2]), __uint_as_float(r[j+3]));
                if (EPI == 1) {
                    const float4 b = *(const float4*)(aux + col);
                    v.x = softplusf(v.x + b.x); v.y = softplusf(v.y + b.y);
                    v.z = softplusf(v.z + b.z); v.w = softplusf(v.w + b.w);
                }
                if (EPI == 2) {
                    const float4 a4 = *(const float4*)(aux + (size_t)m * N + col);
                    v.x += a4.x; v.y += a4.y; v.z += a4.z; v.w += a4.w;
                }
                *(float4*)(C + (size_t)m * N + col) = v;
            }
        }
    }

    __syncthreads();
    if (tid == 0)
        asm volatile("mbarrier.inval.shared.b64 [%0];" :: "r"(sb + 8) : "memory");
    __syncthreads();
    if (warp == 0)
        asm volatile("tcgen05.dealloc.cta_group::1.sync.aligned.b32 %0, %1;"
                     :: "r"(tmem), "r"(128u));
#else
    // ================= mma.sync fallback (any non-'a' pass) — proven R3 body =======
    __shared__ uint32_t sAh[8][136], sAl[8][136], sBh[8][136], sBl[8][136];
    const int tid  = threadIdx.x;
    const int m0   = blockIdx.y << 7;
    const int n0   = blockIdx.x << 7;
    const int lane = tid & 31, warp = tid >> 5;
    const int wm = (warp >> 1) << 6, wn = (warp & 1) << 6;
    const int g  = lane >> 2,  t  = lane & 3;

    float acc[4][8][4];
#pragma unroll
    for (int i = 0; i < 4; i++)
#pragma unroll
        for (int j = 0; j < 8; j++)
#pragma unroll
            for (int q = 0; q < 4; q++) acc[i][j][q] = 0.f;

#pragma unroll 1
    for (int k0 = 0; k0 < K; k0 += 16) {
#pragma unroll
        for (int it = 0; it < 4; it++) {
            const int idx = tid + (it << 7);
            const int r   = idx >> 2;
            const int kc  = (idx & 3) << 2;
            const int k2  = kc >> 1;
            float4 v = *(const float4*)(A + (size_t)(m0 + r) * lda + k0 + kc);
            uint32_t h0 = pack_bf16x2(v.x, v.y);
            uint32_t h1 = pack_bf16x2(v.z, v.w);
            float rx = __uint_as_float(h0 << 16);
            float ry = __uint_as_float(h0 & 0xffff0000u);
            float rz = __uint_as_float(h1 << 16);
            float rw = __uint_as_float(h1 & 0xffff0000u);
            sAh[k2][r]   = h0; sAh[k2+1][r] = h1;
            sAl[k2][r]   = pack_bf16x2(v.x - rx, v.y - ry);
            sAl[k2+1][r] = pack_bf16x2(v.z - rz, v.w - rw);
            float4 w4 = make_float4(0.f, 0.f, 0.f, 0.f);
            if (n0 + r < N) w4 = *(const float4*)(W + (size_t)(n0 + r) * K + k0 + kc);
            uint32_t g0 = pack_bf16x2(w4.x, w4.y);
            uint32_t g1 = pack_bf16x2(w4.z, w4.w);
            float sx = __uint_as_float(g0 << 16);
            float sy = __uint_as_float(g0 & 0xffff0000u);
            float sz = __uint_as_float(g1 << 16);
            float sw = __uint_as_float(g1 & 0xffff0000u);
            sBh[k2][r]   = g0; sBh[k2+1][r] = g1;
            sBl[k2][r]   = pack_bf16x2(w4.x - sx, w4.y - sy);
            sBl[k2+1][r] = pack_bf16x2(w4.z - sz, w4.w - sw);
        }
        __syncthreads();

        uint32_t bh[8][2], bl[8][2];
#pragma unroll
        for (int nt = 0; nt < 8; nt++) {
            const int nb = wn + (nt << 3) + g;
            bh[nt][0] = sBh[t][nb];     bh[nt][1] = sBh[t+4][nb];
            bl[nt][0] = sBl[t][nb];     bl[nt][1] = sBl[t+4][nb];
        }
#pragma unroll
        for (int mt = 0; mt < 4; mt++) {
            const int mb = wm + (mt << 4) + g;
            uint32_t ah[4] = { sAh[t][mb], sAh[t][mb+8], sAh[t+4][mb], sAh[t+4][mb+8] };
            uint32_t al[4] = { sAl[t][mb], sAl[t][mb+8], sAl[t+4][mb], sAl[t+4][mb+8] };
#pragma unroll
            for (int nt = 0; nt < 8; nt++) {
                mma_bf16(acc[mt][nt], ah, bh[nt]);
                mma_bf16(acc[mt][nt], ah, bl[nt]);
                mma_bf16(acc[mt][nt], al, bh[nt]);
            }
        }
        __syncthreads();
    }

#pragma unroll
    for (int mt = 0; mt < 4; mt++) {
        const int r0 = m0 + wm + (mt << 4) + g;
#pragma unroll
        for (int nt = 0; nt < 8; nt++) {
            const int col = n0 + wn + (nt << 3) + (t << 1);
            if (col < N) {
                float v0 = acc[mt][nt][0], v1 = acc[mt][nt][1];
                float v2 = acc[mt][nt][2], v3 = acc[mt][nt][3];
                if (EPI == 1) {
                    const float b0 = __ldg(&aux[col]), b1 = __ldg(&aux[col+1]);
                    v0 = softplusf(v0 + b0); v1 = softplusf(v1 + b1);
                    v2 = softplusf(v2 + b0); v3 = softplusf(v3 + b1);
                }
                if (EPI == 2) {
                    const float2 a0 = *(const float2*)(aux + (size_t)r0 * N + col);
                    const float2 a1 = *(const float2*)(aux + (size_t)(r0+8) * N + col);
                    v0 += a0.x; v1 += a0.y; v2 += a1.x; v3 += a1.y;
                }
                *(float2*)(C + (size_t)r0     * N + col) = make_float2(v0, v1);
                *(float2*)(C + (size_t)(r0+8) * N + col) = make_float2(v2, v3);
            }
        }
    }
#endif
}

// ---------------- depthwise causal/anticausal conv (K=4) + SiLU -------------------
__global__ void conv_silu_kernel(const float* __restrict__ in, int ldin,
                                 const float* __restrict__ w, const float* __restrict__ bias,
                                 float* __restrict__ out, int backward)
{
    const int idx = blockIdx.x * 256 + threadIdx.x;
    const int dd  = idx & (DI - 1);
    const int tok = idx >> 10;
    const int l   = tok & (LL - 1);
    const float* base = in + (size_t)(tok - l) * ldin + dd;
    const float w0 = w[dd*4+0], w1 = w[dd*4+1], w2 = w[dd*4+2], w3 = w[dd*4+3];
    float acc = bias[dd];
    if (!backward) {
        if (l >= 3) acc += base[(size_t)(l-3)*ldin] * w0;
        if (l >= 2) acc += base[(size_t)(l-2)*ldin] * w1;
        if (l >= 1) acc += base[(size_t)(l-1)*ldin] * w2;
        acc += base[(size_t)l*ldin] * w3;
    } else {
        acc += base[(size_t)l*ldin] * w3;
        if (l+1 < LL) acc += base[(size_t)(l+1)*ldin] * w2;
        if (l+2 < LL) acc += base[(size_t)(l+2)*ldin] * w1;
        if (l+3 < LL) acc += base[(size_t)(l+3)*ldin] * w0;
    }
    out[idx] = siluf(acc);
}

// ---------------- selective scan + fused output gating ----------------
__global__ __launch_bounds__(256) void scan_kernel(
    const float* u, const float* __restrict__ dt,
    const float* __restrict__ xdbl, const float* __restrict__ xz,
    const float* __restrict__ Alog, const float* __restrict__ Dp,
    float* yg, int backward)
{
    __shared__ float s_u[64][16], s_dt[64][16], s_B[64][16], s_C[64][16], s_y[64][16];
    const int b     = blockIdx.x >> 6;
    const int dbase = (blockIdx.x & 63) << 4;
    const int tid = threadIdx.x;
    const int dl  = tid >> 4;
    const int n   = tid & 15;
    const int d   = dbase + dl;
    const float a    = -expf(Alog[d * DST + n]);
    const float Dloc = Dp[d];
    float h = 0.f;
    const size_t brow = (size_t)b * LL;

    for (int chunk = 0; chunk < LL / 64; chunk++) {
        const int c0 = chunk << 6;
#pragma unroll
        for (int i = 0; i < 4; i++) {
            const int ii = tid + (i << 8);
            const int tt = ii >> 4, dc = ii & 15;
            const int t = c0 + tt;
            const int l = backward ? (LL - 1 - t) : t;
            const size_t roff = brow + l;
            s_u [tt][dc] = u [roff * DI + dbase + dc];
            s_dt[tt][dc] = dt[roff * DI + dbase + dc];
            s_B [tt][dc] = xdbl[roff * XD + 64 + dc];
            s_C [tt][dc] = xdbl[roff * XD + 80 + dc];
        }
        __syncthreads();
#pragma unroll 8
        for (int tt = 0; tt < 64; tt++) {
            const float dtv = s_dt[tt][dl];
            const float uv  = s_u [tt][dl];
            const float dA  = __expf(dtv * a);
            const float db  = dtv * uv * s_B[tt][n];
            h = fmaf(dA, h, db);
            float yp = h * s_C[tt][n];
            yp += __shfl_xor_sync(0xffffffffu, yp, 8);
            yp += __shfl_xor_sync(0xffffffffu, yp, 4);
            yp += __shfl_xor_sync(0xffffffffu, yp, 2);
            yp += __shfl_xor_sync(0xffffffffu, yp, 1);
            if (n == 0) s_y[tt][dl] = fmaf(uv, Dloc, yp);
        }
        __syncthreads();
#pragma unroll
        for (int i = 0; i < 4; i++) {
            const int ii = tid + (i << 8);
            const int tt = ii >> 4, dc = ii & 15;
            const int t = c0 + tt;
            const int l = backward ? (LL - 1 - t) : t;
            const size_t roff = brow + l;
            const float z = xz[roff * DI2 + DI + dbase + dc];
            yg[roff * DI + dbase + dc] = s_y[tt][dc] * siluf(z);
        }
        __syncthreads();
    }
}

// ---------------- final gate/concat ----------------
__global__ void ymix_kernel(const float* __restrict__ mo0, const float* __restrict__ mo1,
                            const float* __restrict__ xp, float* __restrict__ ym)
{
    const int idx = blockIdx.x * 256 + threadIdx.x;
    const int dd  = idx & (DI - 1);
    const int tok = idx >> 10;
    const float g = siluf(xp[(size_t)tok * DI2 + DI + dd]);
    ym[(size_t)tok * DI2 + dd]      = mo0[idx] * g;
    ym[(size_t)tok * DI2 + DI + dd] = mo1[idx] * g;
}

// ---------------- host ----------------
extern "C" void kernel_launch(void* const* d_in, const int* in_sizes, int n_in,
                              void* d_out, int out_size)
{
    const float* x      = (const float*)d_in[0];
    const float* norm_g = (const float*)d_in[1];
    const float* norm_b = (const float*)d_in[2];
    const float* in_w   = (const float*)d_in[3];
    const float* conv_w = (const float*)d_in[4];
    const float* conv_b = (const float*)d_in[5];
    const float* out_w  = (const float*)d_in[6];
    const float* P[2][9];
    for (int p = 0; p < 2; p++)
        for (int i = 0; i < 9; i++)
            P[p][i] = (const float*)d_in[7 + p * 9 + i];
    // P[p]: 0 in_w, 1 conv_w, 2 conv_b, 3 xp_w, 4 dt_w, 5 dt_b, 6 Alog, 7 D, 8 out_w

    cudaFuncSetAttribute(gemm5<0>, cudaFuncAttributeMaxDynamicSharedMemorySize, SM_TOT);
    cudaFuncSetAttribute(gemm5<1>, cudaFuncAttributeMaxDynamicSharedMemorySize, SM_TOT);
    cudaFuncSetAttribute(gemm5<2>, cudaFuncAttributeMaxDynamicSharedMemorySize, SM_TOT);

    float *xn, *xp, *xa, *xz, *xma, *xdbl, *dtb;
    cudaGetSymbolAddress((void**)&xn,   g_xn);
    cudaGetSymbolAddress((void**)&xp,   g_xp);
    cudaGetSymbolAddress((void**)&xa,   g_xa);
    cudaGetSymbolAddress((void**)&xz,   g_xz);
    cudaGetSymbolAddress((void**)&xma,  g_xma);
    cudaGetSymbolAddress((void**)&xdbl, g_xdbl);
    cudaGetSymbolAddress((void**)&dtb,  g_dt);

    float* mo = dtb;   // alias: dt fully consumed by scan before mamba-out GEMM writes
    float* ym = xz;    // alias: xz[0] fully consumed by p=0 scan's fused gating

    const int EW_GRID = NTOK * DI / 256;
    const int MB = NTOK / 128;   // 64 M-blocks

    ln_kernel<<<NTOK, 128>>>(x, norm_g, norm_b, xn);

    // xp = xn @ in_w^T  (8192 x 2048, K=512)
    gemm5<0><<<dim3(DI2 / 128, MB), 128, SM_TOT>>>(xn, DMODEL, in_w, xp, DI2, DMODEL, nullptr);

    // xa = silu(causal dwconv(xp[:, :DI]))
    conv_silu_kernel<<<EW_GRID, 256>>>(xp, DI2, conv_w, conv_b, xa, 0);

    for (int p = 0; p < 2; p++) {
        float* xzp  = xz   + (size_t)p * NTOK * DI2;
        float* xmap = xma  + (size_t)p * NTOK * DI;
        float* xdp  = xdbl + (size_t)p * NTOK * XD;
        float* dtp  = dtb  + (size_t)p * NTOK * DI;
        float* mop  = mo   + (size_t)p * NTOK * DI;   // same memory as dtp

        // xz = xa @ p_in_w^T  (8192 x 2048, K=1024) — flips pointwise in L, elided
        gemm5<0><<<dim3(DI2 / 128, MB), 128, SM_TOT>>>(xa, DI, P[p][0], xzp, DI2, DI, nullptr);
        // xm = silu(dwconv(xz[:, :DI]))  causal (p=0) / anticausal-reversed (p=1)
        conv_silu_kernel<<<EW_GRID, 256>>>(xzp, DI2, P[p][1], P[p][2], xmap, p);
        // xdbl = xm @ xp_w^T  (8192 x 96, K=1024)
        gemm5<0><<<dim3(1, MB), 128, SM_TOT>>>(xmap, DI, P[p][3], xdp, XD, DI, nullptr);
        // dt = softplus(xdbl[:, :64] @ dt_w^T + dt_b)  (8192 x 1024, K=64, lda=96)
        gemm5<1><<<dim3(DI / 128, MB), 128, SM_TOT>>>(xdp, XD, P[p][4], dtp, DI, DTR, P[p][5]);
        // selective scan + fused  y*silu(z)  gating, in place over xmap
        scan_kernel<<<BN_ * (DI / 16), 256>>>(xmap, dtp, xdp, xzp, P[p][6], P[p][7], xmap, p);
        // mamba out = yg @ out_w^T (8192 x 1024, K=1024); mop aliases dtp (dt dead)
        gemm5<0><<<dim3(DI / 128, MB), 128, SM_TOT>>>(xmap, DI, P[p][8], mop, DI, DI, nullptr);
    }

    // ym = [yf*g, yb*g],  g = silu(xp[:, DI:]); ym aliases xz[0] (dead)
    ymix_kernel<<<EW_GRID, 256>>>(mo, mo + (size_t)NTOK * DI, xp, ym);

    // out = ym @ out_w^T + x  (8192 x 512, K=2048)
    gemm5<2><<<dim3(DMODEL / 128, MB), 128, SM_TOT>>>(ym, DI2, out_w, (float*)d_out, DMODEL, DI2, x);
}